// round 1
// baseline (speedup 1.0000x reference)
#include <cuda_runtime.h>
#include <math.h>

#define E 8
#define D 1024
#define F 4096
#define T 2048

#define BM 128
#define BN 64
#define BK 8
#define TM 8
#define TN 4

// Scratch (device globals — no allocation allowed in kernel_launch)
__device__ int   g_cnt[E];
__device__ int   g_tok[E * T];
__device__ float g_wgt[E * T];
__device__ float g_H[(size_t)E * T * F];   // 256 MB: per-expert hidden activations

// ---------------------------------------------------------------------------
// Zero the per-expert counters (deterministic per launch)
// ---------------------------------------------------------------------------
__global__ void zero_cnt_kernel() {
    if (threadIdx.x < E) g_cnt[threadIdx.x] = 0;
}

// ---------------------------------------------------------------------------
// Router: logits -> top-2 -> renormalized weights -> per-expert token lists
// One warp per token.
// ---------------------------------------------------------------------------
__global__ void router_kernel(const float* __restrict__ x,
                              const float* __restrict__ wr) {
    int t = blockIdx.x * blockDim.y + threadIdx.y;
    if (t >= T) return;
    int lane = threadIdx.x;

    float acc[E];
#pragma unroll
    for (int e = 0; e < E; e++) acc[e] = 0.f;

    const float* xr = x + (size_t)t * D;
    for (int d = lane; d < D; d += 32) {
        float xv = xr[d];
        const float* w = wr + (size_t)d * E;
#pragma unroll
        for (int e = 0; e < E; e++) acc[e] = fmaf(xv, w[e], acc[e]);
    }
#pragma unroll
    for (int off = 16; off > 0; off >>= 1) {
#pragma unroll
        for (int e = 0; e < E; e++)
            acc[e] += __shfl_down_sync(0xffffffffu, acc[e], off);
    }

    if (lane == 0) {
        // top-1 (first occurrence on ties, matching jax top_k)
        int i0 = 0;
#pragma unroll
        for (int e = 1; e < E; e++) if (acc[e] > acc[i0]) i0 = e;
        // top-2
        int i1 = (i0 == 0) ? 1 : 0;
#pragma unroll
        for (int e = 0; e < E; e++) {
            if (e == i0) continue;
            if (acc[e] > acc[i1]) i1 = e;
        }
        float l0 = acc[i0], l1 = acc[i1];
        // renormalized top-2 softmax: w0 = e^l0/(e^l0+e^l1) = sigmoid(l0-l1)
        float w0 = 1.f / (1.f + expf(l1 - l0));
        float w1 = 1.f - w0;

        int p0 = atomicAdd(&g_cnt[i0], 1);
        g_tok[i0 * T + p0] = t;
        g_wgt[i0 * T + p0] = w0;
        int p1 = atomicAdd(&g_cnt[i1], 1);
        g_tok[i1 * T + p1] = t;
        g_wgt[i1 * T + p1] = w1;
    }
}

// ---------------------------------------------------------------------------
// GEMM A: per-expert gathered  H = silu(X @ Wg) * (X @ Wu)
// X gathered rows [cnt_e, D], Wg/Wu [D, F].  Tile BM x BN, dual accumulators.
// ---------------------------------------------------------------------------
__global__ __launch_bounds__(256, 2) void gemmA_kernel(
    const float* __restrict__ x,
    const float* __restrict__ Wg,
    const float* __restrict__ Wu)
{
    int e = blockIdx.z;
    int cnt = g_cnt[e];
    int row0 = blockIdx.y * BM;
    if (row0 >= cnt) return;
    int col0 = blockIdx.x * BN;

    __shared__ float As[BK][BM];
    __shared__ float Bgs[BK][BN];
    __shared__ float Bus[BK][BN];
    __shared__ int   toks[BM];

    int tid = threadIdx.x;
    for (int i = tid; i < BM; i += 256) {
        int r = row0 + i;
        toks[i] = (r < cnt) ? g_tok[e * T + r] : -1;
    }
    __syncthreads();

    int tx = tid & 15;   // N direction (16 x TN=4 -> 64)
    int ty = tid >> 4;   // M direction (16 x TM=8 -> 128)

    float accg[TM][TN], accu[TM][TN];
#pragma unroll
    for (int m = 0; m < TM; m++)
#pragma unroll
        for (int n = 0; n < TN; n++) { accg[m][n] = 0.f; accu[m][n] = 0.f; }

    // A-load assignment: 128 rows x 8 k, float4 per thread
    int ar = tid >> 1;
    int ak = (tid & 1) * 4;
    int tokA = toks[ar];

    const float* wg_base = Wg + (size_t)e * D * F + col0;
    const float* wu_base = Wu + (size_t)e * D * F + col0;

    for (int k0 = 0; k0 < D; k0 += BK) {
        float4 av = make_float4(0.f, 0.f, 0.f, 0.f);
        if (tokA >= 0)
            av = *(const float4*)(x + (size_t)tokA * D + k0 + ak);
        As[ak + 0][ar] = av.x;
        As[ak + 1][ar] = av.y;
        As[ak + 2][ar] = av.z;
        As[ak + 3][ar] = av.w;

#pragma unroll
        for (int rep = 0; rep < 2; rep++) {
            int idx = tid + rep * 256;
            int kk = idx >> 6;
            int c  = idx & 63;
            Bgs[kk][c] = wg_base[(size_t)(k0 + kk) * F + c];
            Bus[kk][c] = wu_base[(size_t)(k0 + kk) * F + c];
        }
        __syncthreads();

#pragma unroll
        for (int kk = 0; kk < BK; kk++) {
            float4 a0 = *(const float4*)&As[kk][ty * TM];
            float4 a1 = *(const float4*)&As[kk][ty * TM + 4];
            float4 bg = *(const float4*)&Bgs[kk][tx * TN];
            float4 bu = *(const float4*)&Bus[kk][tx * TN];
            float a[TM] = {a0.x, a0.y, a0.z, a0.w, a1.x, a1.y, a1.z, a1.w};
            float bgv[TN] = {bg.x, bg.y, bg.z, bg.w};
            float buv[TN] = {bu.x, bu.y, bu.z, bu.w};
#pragma unroll
            for (int m = 0; m < TM; m++) {
#pragma unroll
                for (int n = 0; n < TN; n++) {
                    accg[m][n] = fmaf(a[m], bgv[n], accg[m][n]);
                    accu[m][n] = fmaf(a[m], buv[n], accu[m][n]);
                }
            }
        }
        __syncthreads();
    }

    // Epilogue: h = silu(g) * u
#pragma unroll
    for (int m = 0; m < TM; m++) {
        int r = row0 + ty * TM + m;
        if (r >= cnt) continue;
        float* hrow = g_H + ((size_t)e * T + r) * F + col0 + tx * TN;
#pragma unroll
        for (int n = 0; n < TN; n++) {
            float g = accg[m][n];
            float s = g / (1.f + expf(-g));
            hrow[n] = s * accu[m][n];
        }
    }
}

// ---------------------------------------------------------------------------
// GEMM B: per-expert  out[tok] += w_tok * (H_e @ Wd_e)
// H rows [cnt_e, F], Wd [F, D]. atomicAdd combine (2 adds/elem, fp32 add is
// commutative -> deterministic).
// ---------------------------------------------------------------------------
__global__ __launch_bounds__(256, 2) void gemmB_kernel(
    const float* __restrict__ Wd,
    float* __restrict__ out)
{
    int e = blockIdx.z;
    int cnt = g_cnt[e];
    int row0 = blockIdx.y * BM;
    if (row0 >= cnt) return;
    int col0 = blockIdx.x * BN;

    __shared__ float As[BK][BM];
    __shared__ float Bs[BK][BN];
    __shared__ int   toks[BM];
    __shared__ float wts[BM];

    int tid = threadIdx.x;
    for (int i = tid; i < BM; i += 256) {
        int r = row0 + i;
        toks[i] = (r < cnt) ? g_tok[e * T + r] : -1;
        wts[i]  = (r < cnt) ? g_wgt[e * T + r] : 0.f;
    }
    __syncthreads();

    int tx = tid & 15;
    int ty = tid >> 4;

    float acc[TM][TN];
#pragma unroll
    for (int m = 0; m < TM; m++)
#pragma unroll
        for (int n = 0; n < TN; n++) acc[m][n] = 0.f;

    int ar = tid >> 1;
    int ak = (tid & 1) * 4;
    bool arow_ok = (row0 + ar) < cnt;
    const float* hsrc = g_H + ((size_t)e * T + row0 + ar) * F + ak;

    const float* wd_base = Wd + (size_t)e * F * D + col0;

    for (int k0 = 0; k0 < F; k0 += BK) {
        float4 av = make_float4(0.f, 0.f, 0.f, 0.f);
        if (arow_ok)
            av = *(const float4*)(hsrc + k0);
        As[ak + 0][ar] = av.x;
        As[ak + 1][ar] = av.y;
        As[ak + 2][ar] = av.z;
        As[ak + 3][ar] = av.w;

#pragma unroll
        for (int rep = 0; rep < 2; rep++) {
            int idx = tid + rep * 256;
            int kk = idx >> 6;
            int c  = idx & 63;
            Bs[kk][c] = wd_base[(size_t)(k0 + kk) * D + c];
        }
        __syncthreads();

#pragma unroll
        for (int kk = 0; kk < BK; kk++) {
            float4 a0 = *(const float4*)&As[kk][ty * TM];
            float4 a1 = *(const float4*)&As[kk][ty * TM + 4];
            float4 bv = *(const float4*)&Bs[kk][tx * TN];
            float a[TM] = {a0.x, a0.y, a0.z, a0.w, a1.x, a1.y, a1.z, a1.w};
            float b[TN] = {bv.x, bv.y, bv.z, bv.w};
#pragma unroll
            for (int m = 0; m < TM; m++)
#pragma unroll
                for (int n = 0; n < TN; n++)
                    acc[m][n] = fmaf(a[m], b[n], acc[m][n]);
        }
        __syncthreads();
    }

#pragma unroll
    for (int m = 0; m < TM; m++) {
        int r = row0 + ty * TM + m;
        if (r >= cnt) continue;
        int tok = toks[ty * TM + m];
        float w = wts[ty * TM + m];
        float* orow = out + (size_t)tok * D + col0 + tx * TN;
#pragma unroll
        for (int n = 0; n < TN; n++)
            atomicAdd(&orow[n], acc[m][n] * w);
    }
}

// ---------------------------------------------------------------------------
// Launch
// ---------------------------------------------------------------------------
extern "C" void kernel_launch(void* const* d_in, const int* in_sizes, int n_in,
                              void* d_out, int out_size) {
    const float* x  = (const float*)d_in[0];   // [T, D]
    const float* wr = (const float*)d_in[1];   // [D, E]
    const float* wg = (const float*)d_in[2];   // [E, D, F]
    const float* wu = (const float*)d_in[3];   // [E, D, F]
    const float* wd = (const float*)d_in[4];   // [E, F, D]
    float* out = (float*)d_out;                // [T, D]

    cudaMemsetAsync(out, 0, (size_t)T * D * sizeof(float), 0);
    zero_cnt_kernel<<<1, 32>>>();
    router_kernel<<<T / 8, dim3(32, 8)>>>(x, wr);
    gemmA_kernel<<<dim3(F / BN, T / BM, E), 256>>>(x, wg, wu);
    gemmB_kernel<<<dim3(D / BN, T / BM, E), 256>>>(wd, out);
}

// round 3
// speedup vs baseline: 3.1938x; 3.1938x over previous
#include <cuda_runtime.h>
#include <math.h>
#include <stdint.h>

#define E 8
#define D 1024
#define F 4096
#define T 2048
#define RMAX 2048

// ---------------------------------------------------------------------------
// Device scratch
// ---------------------------------------------------------------------------
__device__ int   g_cnt[E];
__device__ int   g_tok[E * T];
__device__ float g_wgt[E * T];
__device__ float g_H[(size_t)E * RMAX * F];   // 256 MB hidden activations

// ---------------------------------------------------------------------------
// Helpers
// ---------------------------------------------------------------------------
__device__ __forceinline__ float tfbits(float f) {
    uint32_t r;
    asm("cvt.rna.tf32.f32 %0, %1;" : "=r"(r) : "f"(f));
    return __uint_as_float(r);
}

// m16n8k8 tf32 mma: D = A(16x8,row) * B(8x8,col) + D
__device__ __forceinline__ void mma8(float c[4], const uint32_t a[4],
                                     uint32_t b0, uint32_t b1) {
    asm volatile(
        "mma.sync.aligned.m16n8k8.row.col.f32.tf32.tf32.f32 "
        "{%0,%1,%2,%3}, {%4,%5,%6,%7}, {%8,%9}, {%0,%1,%2,%3};"
        : "+f"(c[0]), "+f"(c[1]), "+f"(c[2]), "+f"(c[3])
        : "r"(a[0]), "r"(a[1]), "r"(a[2]), "r"(a[3]), "r"(b0), "r"(b1));
}

// ---------------------------------------------------------------------------
// Router (identical to the passing R1 version)
// ---------------------------------------------------------------------------
__global__ void zero_cnt_kernel() {
    if (threadIdx.x < E) g_cnt[threadIdx.x] = 0;
}

__global__ void router_kernel(const float* __restrict__ x,
                              const float* __restrict__ wr) {
    int t = blockIdx.x * blockDim.y + threadIdx.y;
    if (t >= T) return;
    int lane = threadIdx.x;
    float acc[E];
#pragma unroll
    for (int e = 0; e < E; e++) acc[e] = 0.f;
    const float* xr = x + (size_t)t * D;
    for (int d = lane; d < D; d += 32) {
        float xv = xr[d];
        const float* w = wr + (size_t)d * E;
#pragma unroll
        for (int e = 0; e < E; e++) acc[e] = fmaf(xv, w[e], acc[e]);
    }
#pragma unroll
    for (int off = 16; off > 0; off >>= 1)
#pragma unroll
        for (int e = 0; e < E; e++)
            acc[e] += __shfl_down_sync(0xffffffffu, acc[e], off);

    if (lane == 0) {
        int i0 = 0;
#pragma unroll
        for (int e = 1; e < E; e++) if (acc[e] > acc[i0]) i0 = e;
        int i1 = (i0 == 0) ? 1 : 0;
#pragma unroll
        for (int e = 0; e < E; e++) {
            if (e == i0) continue;
            if (acc[e] > acc[i1]) i1 = e;
        }
        float w0 = 1.f / (1.f + expf(acc[i1] - acc[i0]));
        float w1 = 1.f - w0;
        int p0 = atomicAdd(&g_cnt[i0], 1);
        g_tok[i0 * T + p0] = t;  g_wgt[i0 * T + p0] = w0;
        int p1 = atomicAdd(&g_cnt[i1], 1);
        g_tok[i1 * T + p1] = t;  g_wgt[i1 * T + p1] = w1;
    }
}

// ---------------------------------------------------------------------------
// GEMM A (mma.sync tf32): H = silu(X@Wg) * (X@Wu), gathered rows per expert.
// CTA tile: M=128 x N=64 (both gate & up). 8 warps = 4M x 2N, warp 32x32 x2.
// A smem [m][k] pitch 36 fl; B smem [k][n] pitch 72 fl. K-chunk 32, 2 stages.
// ---------------------------------------------------------------------------
#define GA_STAGE_FL 9216               // 128*36 + 2*32*72 floats
#define GA_SMEM (512 + 2 * GA_STAGE_FL * 4)

__global__ void __launch_bounds__(256, 2) gemmA_mma(
    const float* __restrict__ x,
    const float* __restrict__ Wg,
    const float* __restrict__ Wu)
{
    extern __shared__ char smem[];
    const int e = blockIdx.z;
    const int cnt = g_cnt[e];
    const int row0 = blockIdx.x * 128;
    if (row0 >= cnt) return;
    const int col0 = blockIdx.y * 64;

    int* toks = (int*)smem;
    const int tid = threadIdx.x;
    if (tid < 128) {
        int r = row0 + tid;
        toks[tid] = (r < cnt) ? g_tok[e * T + r] : -1;
    }
    __syncthreads();

    const int wid = tid >> 5, lane = tid & 31;
    const int g = lane >> 2, tg = lane & 3;
    const int m0w = (wid >> 1) * 32, n0w = (wid & 1) * 32;

    const float* wg_base = Wg + (size_t)e * D * F + col0;
    const float* wu_base = Wu + (size_t)e * D * F + col0;

    float accg[2][4][4], accu[2][4][4];
#pragma unroll
    for (int mt = 0; mt < 2; mt++)
#pragma unroll
        for (int nt = 0; nt < 4; nt++)
#pragma unroll
            for (int j = 0; j < 4; j++) { accg[mt][nt][j] = 0.f; accu[mt][nt][j] = 0.f; }

    float4 ra[4], rg[2], ru[2];

    auto LDGC = [&](int c) {
#pragma unroll
        for (int i = 0; i < 4; i++) {
            int idx = tid + (i << 8);
            int m = idx >> 3, q = idx & 7;
            int tk = toks[m];
            ra[i] = (tk >= 0)
                ? *(const float4*)(x + (size_t)tk * D + c * 32 + (q << 2))
                : make_float4(0.f, 0.f, 0.f, 0.f);
        }
#pragma unroll
        for (int i = 0; i < 2; i++) {
            int idx = tid + (i << 8);
            int kk = idx >> 4, nq = idx & 15;
            size_t o = (size_t)(c * 32 + kk) * F + (nq << 2);
            rg[i] = *(const float4*)(wg_base + o);
            ru[i] = *(const float4*)(wu_base + o);
        }
    };
    auto STSC = [&](int buf) {
        float* fb = (float*)(smem + 512) + buf * GA_STAGE_FL;
#pragma unroll
        for (int i = 0; i < 4; i++) {
            int idx = tid + (i << 8);
            int m = idx >> 3, q = idx & 7;
            float4 v = make_float4(tfbits(ra[i].x), tfbits(ra[i].y),
                                   tfbits(ra[i].z), tfbits(ra[i].w));
            *(float4*)(fb + m * 36 + (q << 2)) = v;
        }
#pragma unroll
        for (int i = 0; i < 2; i++) {
            int idx = tid + (i << 8);
            int kk = idx >> 4, nq = idx & 15;
            float* pg = fb + 4608 + kk * 72 + (nq << 2);
            float4 vg = make_float4(tfbits(rg[i].x), tfbits(rg[i].y),
                                    tfbits(rg[i].z), tfbits(rg[i].w));
            float4 vu = make_float4(tfbits(ru[i].x), tfbits(ru[i].y),
                                    tfbits(ru[i].z), tfbits(ru[i].w));
            *(float4*)pg = vg;
            *(float4*)(pg + 2304) = vu;
        }
    };
    auto COMPUTE = [&](int buf) {
        const float* fb = (const float*)(smem + 512) + buf * GA_STAGE_FL;
        const float* sA = fb;
        const float* sB = fb + 4608;
#pragma unroll
        for (int ks = 0; ks < 4; ks++) {
            uint32_t a[2][4];
#pragma unroll
            for (int mt = 0; mt < 2; mt++) {
                const float* ap = sA + (m0w + 16 * mt + g) * 36 + 8 * ks + tg;
                a[mt][0] = __float_as_uint(ap[0]);
                a[mt][1] = __float_as_uint(ap[8 * 36]);
                a[mt][2] = __float_as_uint(ap[4]);
                a[mt][3] = __float_as_uint(ap[8 * 36 + 4]);
            }
#pragma unroll
            for (int nt = 0; nt < 4; nt++) {
                const float* bp = sB + (8 * ks + tg) * 72 + n0w + 8 * nt + g;
                uint32_t bg0 = __float_as_uint(bp[0]);
                uint32_t bg1 = __float_as_uint(bp[4 * 72]);
                uint32_t bu0 = __float_as_uint(bp[2304]);
                uint32_t bu1 = __float_as_uint(bp[2304 + 4 * 72]);
#pragma unroll
                for (int mt = 0; mt < 2; mt++) {
                    mma8(accg[mt][nt], a[mt], bg0, bg1);
                    mma8(accu[mt][nt], a[mt], bu0, bu1);
                }
            }
        }
    };

    LDGC(0);
    STSC(0);
    __syncthreads();
#pragma unroll 1
    for (int c = 1; c < 32; c++) {
        LDGC(c);
        COMPUTE((c - 1) & 1);
        STSC(c & 1);
        __syncthreads();
    }
    COMPUTE(1);

    // --- epilogue: silu(gate)*up -> g_H ---
#pragma unroll
    for (int mt = 0; mt < 2; mt++) {
#pragma unroll
        for (int rh = 0; rh < 2; rh++) {
            int r = row0 + m0w + 16 * mt + 8 * rh + g;
            if (r < cnt) {
                float* hrow = g_H + ((size_t)e * RMAX + r) * F + col0 + n0w + 2 * tg;
#pragma unroll
                for (int nt = 0; nt < 4; nt++) {
                    float g0 = accg[mt][nt][2 * rh], g1 = accg[mt][nt][2 * rh + 1];
                    float u0 = accu[mt][nt][2 * rh], u1 = accu[mt][nt][2 * rh + 1];
                    float2 o;
                    o.x = (g0 / (1.f + __expf(-g0))) * u0;
                    o.y = (g1 / (1.f + __expf(-g1))) * u1;
                    *(float2*)(hrow + 8 * nt) = o;
                }
            }
        }
    }
}

// ---------------------------------------------------------------------------
// GEMM B (mma.sync tf32): out[tok] += w * (H @ Wd).
// CTA tile: M=128 x N=128. 8 warps = 4M x 2N, warp 32x64. K=4096, chunk 32.
// A smem [m][k] pitch 36; B smem [k][n] pitch 136. atomicAdd combine.
// ---------------------------------------------------------------------------
#define GB_STAGE_FL 8960               // 128*36 + 32*136 floats
#define GB_SMEM (1024 + 2 * GB_STAGE_FL * 4)

__global__ void __launch_bounds__(256, 2) gemmB_mma(
    const float* __restrict__ Wd,
    float* __restrict__ out)
{
    extern __shared__ char smem[];
    const int e = blockIdx.z;
    const int cnt = g_cnt[e];
    const int row0 = blockIdx.x * 128;
    if (row0 >= cnt) return;
    const int col0 = blockIdx.y * 128;

    int*   toks = (int*)smem;
    float* wts  = (float*)(smem + 512);
    const int tid = threadIdx.x;
    if (tid < 128) {
        int r = row0 + tid;
        toks[tid] = (r < cnt) ? g_tok[e * T + r] : 0;
        wts[tid]  = (r < cnt) ? g_wgt[e * T + r] : 0.f;
    }
    __syncthreads();

    const int wid = tid >> 5, lane = tid & 31;
    const int g = lane >> 2, tg = lane & 3;
    const int m0w = (wid >> 1) * 32, n0w = (wid & 1) * 64;

    const float* wd_base = Wd + (size_t)e * F * D + col0;
    const float* h_base  = g_H + (size_t)e * RMAX * F;

    float acc[2][8][4];
#pragma unroll
    for (int mt = 0; mt < 2; mt++)
#pragma unroll
        for (int nt = 0; nt < 8; nt++)
#pragma unroll
            for (int j = 0; j < 4; j++) acc[mt][nt][j] = 0.f;

    float4 ra[4], rb[4];

    auto LDGC = [&](int c) {
#pragma unroll
        for (int i = 0; i < 4; i++) {
            int idx = tid + (i << 8);
            int m = idx >> 3, q = idx & 7;
            int r = row0 + m;
            ra[i] = (r < cnt)
                ? *(const float4*)(h_base + (size_t)r * F + c * 32 + (q << 2))
                : make_float4(0.f, 0.f, 0.f, 0.f);
        }
#pragma unroll
        for (int i = 0; i < 4; i++) {
            int idx = tid + (i << 8);
            int kk = idx >> 5, nq = idx & 31;
            rb[i] = *(const float4*)(wd_base + (size_t)(c * 32 + kk) * D + (nq << 2));
        }
    };
    auto STSC = [&](int buf) {
        float* fb = (float*)(smem + 1024) + buf * GB_STAGE_FL;
#pragma unroll
        for (int i = 0; i < 4; i++) {
            int idx = tid + (i << 8);
            int m = idx >> 3, q = idx & 7;
            float4 v = make_float4(tfbits(ra[i].x), tfbits(ra[i].y),
                                   tfbits(ra[i].z), tfbits(ra[i].w));
            *(float4*)(fb + m * 36 + (q << 2)) = v;
        }
#pragma unroll
        for (int i = 0; i < 4; i++) {
            int idx = tid + (i << 8);
            int kk = idx >> 5, nq = idx & 31;
            float4 v = make_float4(tfbits(rb[i].x), tfbits(rb[i].y),
                                   tfbits(rb[i].z), tfbits(rb[i].w));
            *(float4*)(fb + 4608 + kk * 136 + (nq << 2)) = v;
        }
    };
    auto COMPUTE = [&](int buf) {
        const float* fb = (const float*)(smem + 1024) + buf * GB_STAGE_FL;
        const float* sA = fb;
        const float* sB = fb + 4608;
#pragma unroll
        for (int ks = 0; ks < 4; ks++) {
            uint32_t a[2][4];
#pragma unroll
            for (int mt = 0; mt < 2; mt++) {
                const float* ap = sA + (m0w + 16 * mt + g) * 36 + 8 * ks + tg;
                a[mt][0] = __float_as_uint(ap[0]);
                a[mt][1] = __float_as_uint(ap[8 * 36]);
                a[mt][2] = __float_as_uint(ap[4]);
                a[mt][3] = __float_as_uint(ap[8 * 36 + 4]);
            }
#pragma unroll
            for (int nt = 0; nt < 8; nt++) {
                const float* bp = sB + (8 * ks + tg) * 136 + n0w + 8 * nt + g;
                uint32_t b0 = __float_as_uint(bp[0]);
                uint32_t b1 = __float_as_uint(bp[4 * 136]);
#pragma unroll
                for (int mt = 0; mt < 2; mt++)
                    mma8(acc[mt][nt], a[mt], b0, b1);
            }
        }
    };

    LDGC(0);
    STSC(0);
    __syncthreads();
#pragma unroll 1
    for (int c = 1; c < 128; c++) {
        LDGC(c);
        COMPUTE((c - 1) & 1);
        STSC(c & 1);
        __syncthreads();
    }
    COMPUTE(1);   // chunk 127 lives in buffer 1

    // --- epilogue: weighted atomicAdd combine ---
#pragma unroll
    for (int mt = 0; mt < 2; mt++) {
#pragma unroll
        for (int rh = 0; rh < 2; rh++) {
            int rloc = m0w + 16 * mt + 8 * rh + g;
            if (row0 + rloc < cnt) {
                int tok = toks[rloc];
                float w = wts[rloc];
                float* orow = out + (size_t)tok * D + col0 + n0w + 2 * tg;
#pragma unroll
                for (int nt = 0; nt < 8; nt++) {
                    atomicAdd(orow + 8 * nt,     acc[mt][nt][2 * rh] * w);
                    atomicAdd(orow + 8 * nt + 1, acc[mt][nt][2 * rh + 1] * w);
                }
            }
        }
    }
}

// ---------------------------------------------------------------------------
// Launch
// ---------------------------------------------------------------------------
extern "C" void kernel_launch(void* const* d_in, const int* in_sizes, int n_in,
                              void* d_out, int out_size) {
    const float* x  = (const float*)d_in[0];
    const float* wr = (const float*)d_in[1];
    const float* wg = (const float*)d_in[2];
    const float* wu = (const float*)d_in[3];
    const float* wd = (const float*)d_in[4];
    float* out = (float*)d_out;

    cudaFuncSetAttribute(gemmA_mma, cudaFuncAttributeMaxDynamicSharedMemorySize, GA_SMEM);
    cudaFuncSetAttribute(gemmB_mma, cudaFuncAttributeMaxDynamicSharedMemorySize, GB_SMEM);

    cudaMemsetAsync(out, 0, (size_t)T * D * sizeof(float), 0);
    zero_cnt_kernel<<<1, 32>>>();
    router_kernel<<<T / 8, dim3(32, 8)>>>(x, wr);
    gemmA_mma<<<dim3(T / 128, F / 64, E), 256, GA_SMEM>>>(x, wg, wu);
    gemmB_mma<<<dim3(T / 128, D / 128, E), 256, GB_SMEM>>>(wd, out);
}

// round 4
// speedup vs baseline: 5.2005x; 1.6283x over previous
#include <cuda_runtime.h>
#include <cuda_fp16.h>
#include <math.h>
#include <stdint.h>

#define E 8
#define D 1024
#define F 4096
#define T 2048
#define RMAX 2048

// ---------------------------------------------------------------------------
// Device scratch
// ---------------------------------------------------------------------------
__device__ int   g_cnt[E];
__device__ int   g_tok[E * T];
__device__ float g_wgt[E * T];
__device__ __align__(16) __half g_H[(size_t)E * RMAX * F];   // 128 MB

// ---------------------------------------------------------------------------
// Helpers
// ---------------------------------------------------------------------------
__device__ __forceinline__ uint32_t packh2(float a, float b) {
    __half2 h = __floats2half2_rn(a, b);
    return *(uint32_t*)&h;
}
__device__ __forceinline__ void mma16(float c[4], const uint32_t a[4],
                                      uint32_t b0, uint32_t b1) {
    asm volatile(
        "mma.sync.aligned.m16n8k16.row.col.f32.f16.f16.f32 "
        "{%0,%1,%2,%3}, {%4,%5,%6,%7}, {%8,%9}, {%0,%1,%2,%3};"
        : "+f"(c[0]), "+f"(c[1]), "+f"(c[2]), "+f"(c[3])
        : "r"(a[0]), "r"(a[1]), "r"(a[2]), "r"(a[3]), "r"(b0), "r"(b1));
}
__device__ __forceinline__ void ldsm4(uint32_t r[4], uint32_t addr) {
    asm volatile("ldmatrix.sync.aligned.m8n8.x4.shared.b16 {%0,%1,%2,%3}, [%4];"
                 : "=r"(r[0]), "=r"(r[1]), "=r"(r[2]), "=r"(r[3]) : "r"(addr));
}
__device__ __forceinline__ void ldsm4t(uint32_t r[4], uint32_t addr) {
    asm volatile("ldmatrix.sync.aligned.m8n8.x4.trans.shared.b16 {%0,%1,%2,%3}, [%4];"
                 : "=r"(r[0]), "=r"(r[1]), "=r"(r[2]), "=r"(r[3]) : "r"(addr));
}

// ---------------------------------------------------------------------------
// Router (unchanged — passing since R1)
// ---------------------------------------------------------------------------
__global__ void zero_cnt_kernel() {
    if (threadIdx.x < E) g_cnt[threadIdx.x] = 0;
}

__global__ void router_kernel(const float* __restrict__ x,
                              const float* __restrict__ wr) {
    int t = blockIdx.x * blockDim.y + threadIdx.y;
    if (t >= T) return;
    int lane = threadIdx.x;
    float acc[E];
#pragma unroll
    for (int e = 0; e < E; e++) acc[e] = 0.f;
    const float* xr = x + (size_t)t * D;
    for (int d = lane; d < D; d += 32) {
        float xv = xr[d];
        const float* w = wr + (size_t)d * E;
#pragma unroll
        for (int e = 0; e < E; e++) acc[e] = fmaf(xv, w[e], acc[e]);
    }
#pragma unroll
    for (int off = 16; off > 0; off >>= 1)
#pragma unroll
        for (int e = 0; e < E; e++)
            acc[e] += __shfl_down_sync(0xffffffffu, acc[e], off);

    if (lane == 0) {
        int i0 = 0;
#pragma unroll
        for (int e = 1; e < E; e++) if (acc[e] > acc[i0]) i0 = e;
        int i1 = (i0 == 0) ? 1 : 0;
#pragma unroll
        for (int e = 0; e < E; e++) {
            if (e == i0) continue;
            if (acc[e] > acc[i1]) i1 = e;
        }
        float w0 = 1.f / (1.f + expf(acc[i1] - acc[i0]));
        float w1 = 1.f - w0;
        int p0 = atomicAdd(&g_cnt[i0], 1);
        g_tok[i0 * T + p0] = t;  g_wgt[i0 * T + p0] = w0;
        int p1 = atomicAdd(&g_cnt[i1], 1);
        g_tok[i1 * T + p1] = t;  g_wgt[i1 * T + p1] = w1;
    }
}

// ---------------------------------------------------------------------------
// GEMM A (fp16 mma + ldmatrix): H = silu(X@Wg) * (X@Wu)  -> g_H (fp16)
// CTA 128 tokens x 64 f-cols (gate & up). 8 warps 4Mx2N, warp 32x32 x2 mats.
// A smem: [m][k] 64B rows, chunk swizzle kc^=(m&3). Bg/Bu: [k][n] 128B rows,
// nc^=(k&7). K-chunk 32, 2 stages.
// ---------------------------------------------------------------------------
#define GA_STAGE 16384              // A 8K + Bg 4K + Bu 4K
#define GA_SMEM (512 + 2 * GA_STAGE)

__global__ void __launch_bounds__(256, 2) gemmA_h(
    const float* __restrict__ x,
    const float* __restrict__ Wg,
    const float* __restrict__ Wu)
{
    extern __shared__ char smem[];
    const int e = blockIdx.z;
    const int cnt = g_cnt[e];
    const int row0 = blockIdx.x * 128;
    if (row0 >= cnt) return;
    const int col0 = blockIdx.y * 64;

    int* toks = (int*)smem;
    const int tid = threadIdx.x;
    if (tid < 128) {
        int r = row0 + tid;
        toks[tid] = (r < cnt) ? g_tok[e * T + r] : -1;
    }
    __syncthreads();

    const int wid = tid >> 5, lane = tid & 31;
    const int g = lane >> 2, tg = lane & 3;
    const int m0w = (wid >> 1) * 32, n0w = (wid & 1) * 32;
    const uint32_t sb = (uint32_t)__cvta_generic_to_shared(smem);

    const float* wg_base = Wg + (size_t)e * D * F + col0;
    const float* wu_base = Wu + (size_t)e * D * F + col0;

    float accg[2][4][4], accu[2][4][4];
#pragma unroll
    for (int mt = 0; mt < 2; mt++)
#pragma unroll
        for (int nt = 0; nt < 4; nt++)
#pragma unroll
            for (int j = 0; j < 4; j++) { accg[mt][nt][j] = 0.f; accu[mt][nt][j] = 0.f; }

    // per-lane ldmatrix address components
    const int lrow = lane & 15;              // row within 16-block
    const int lhk  = lane >> 4;              // 0/1: low/high 8-k (or n) chunk
    float4 ra[4], rg[2], ru[2];

    auto LDGC = [&](int c) {
#pragma unroll
        for (int i = 0; i < 4; i++) {
            int idx = tid + (i << 8);
            int m = idx >> 3, q = idx & 7;
            int tk = toks[m];
            ra[i] = (tk >= 0)
                ? *(const float4*)(x + (size_t)tk * D + c * 32 + (q << 2))
                : make_float4(0.f, 0.f, 0.f, 0.f);
        }
#pragma unroll
        for (int i = 0; i < 2; i++) {
            int idx = tid + (i << 8);
            int kk = idx >> 4, nq = idx & 15;
            size_t o = (size_t)(c * 32 + kk) * F + (nq << 2);
            rg[i] = *(const float4*)(wg_base + o);
            ru[i] = *(const float4*)(wu_base + o);
        }
    };
    auto STSC = [&](int buf) {
        char* fb = smem + 512 + buf * GA_STAGE;
#pragma unroll
        for (int i = 0; i < 4; i++) {
            int idx = tid + (i << 8);
            int m = idx >> 3, q = idx & 7;
            uint2 v = make_uint2(packh2(ra[i].x, ra[i].y), packh2(ra[i].z, ra[i].w));
            *(uint2*)(fb + m * 64 + ((((q >> 1) ^ (m & 3)) << 4) | ((q & 1) << 3))) = v;
        }
#pragma unroll
        for (int i = 0; i < 2; i++) {
            int idx = tid + (i << 8);
            int kk = idx >> 4, nq = idx & 15;
            uint32_t off = kk * 128 + ((((nq >> 1) ^ (kk & 7)) << 4) | ((nq & 1) << 3));
            *(uint2*)(fb + 8192 + off) =
                make_uint2(packh2(rg[i].x, rg[i].y), packh2(rg[i].z, rg[i].w));
            *(uint2*)(fb + 12288 + off) =
                make_uint2(packh2(ru[i].x, ru[i].y), packh2(ru[i].z, ru[i].w));
        }
    };
    auto COMPUTE = [&](int buf) {
        const uint32_t sA = sb + 512 + buf * GA_STAGE;
        const uint32_t sB = sA + 8192;
#pragma unroll
        for (int ks = 0; ks < 2; ks++) {
            uint32_t a[2][4];
#pragma unroll
            for (int mt = 0; mt < 2; mt++) {
                int row = m0w + 16 * mt + lrow;
                int kc = (ks * 2 + lhk) ^ (row & 3);
                ldsm4(a[mt], sA + row * 64 + (kc << 4));
            }
#pragma unroll
            for (int p = 0; p < 2; p++) {
                int k = ks * 16 + lrow;
                int nc = ((n0w >> 3) + 2 * p + lhk) ^ (k & 7);
                uint32_t bg[4], bu[4];
                uint32_t boff = k * 128 + (nc << 4);
                ldsm4t(bg, sB + boff);
                ldsm4t(bu, sB + 4096 + boff);
#pragma unroll
                for (int mt = 0; mt < 2; mt++) {
                    mma16(accg[mt][2 * p],     a[mt], bg[0], bg[1]);
                    mma16(accg[mt][2 * p + 1], a[mt], bg[2], bg[3]);
                    mma16(accu[mt][2 * p],     a[mt], bu[0], bu[1]);
                    mma16(accu[mt][2 * p + 1], a[mt], bu[2], bu[3]);
                }
            }
        }
    };

    LDGC(0);
    STSC(0);
    __syncthreads();
#pragma unroll 1
    for (int c = 1; c < 32; c++) {
        LDGC(c);
        COMPUTE((c - 1) & 1);
        STSC(c & 1);
        __syncthreads();
    }
    COMPUTE(1);

    // --- epilogue: silu(gate)*up -> g_H (fp16) ---
#pragma unroll
    for (int mt = 0; mt < 2; mt++) {
#pragma unroll
        for (int rh = 0; rh < 2; rh++) {
            int r = row0 + m0w + 16 * mt + 8 * rh + g;
            if (r < cnt) {
                __half* hrow = g_H + ((size_t)e * RMAX + r) * F + col0 + n0w + 2 * tg;
#pragma unroll
                for (int nt = 0; nt < 4; nt++) {
                    float g0 = accg[mt][nt][2 * rh], g1 = accg[mt][nt][2 * rh + 1];
                    float u0 = accu[mt][nt][2 * rh], u1 = accu[mt][nt][2 * rh + 1];
                    float o0 = (g0 / (1.f + __expf(-g0))) * u0;
                    float o1 = (g1 / (1.f + __expf(-g1))) * u1;
                    *(__half2*)(hrow + 8 * nt) = __floats2half2_rn(o0, o1);
                }
            }
        }
    }
}

// ---------------------------------------------------------------------------
// GEMM B (fp16 mma + ldmatrix): out[tok] += w * (H @ Wd)
// CTA 128 x 128. 8 warps 4Mx2N, warp 32x64. K=4096, chunk 32, 2 stages.
// A smem [m][k] 64B rows; B smem [k][n] 256B rows, nc^=(k&7).
// ---------------------------------------------------------------------------
#define GB_STAGE 16384              // A 8K + B 8K
#define GB_SMEM (1024 + 2 * GB_STAGE)

__global__ void __launch_bounds__(256, 2) gemmB_h(
    const float* __restrict__ Wd,
    float* __restrict__ out)
{
    extern __shared__ char smem[];
    const int e = blockIdx.z;
    const int cnt = g_cnt[e];
    const int row0 = blockIdx.x * 128;
    if (row0 >= cnt) return;
    const int col0 = blockIdx.y * 128;

    int*   toks = (int*)smem;
    float* wts  = (float*)(smem + 512);
    const int tid = threadIdx.x;
    if (tid < 128) {
        int r = row0 + tid;
        toks[tid] = (r < cnt) ? g_tok[e * T + r] : 0;
        wts[tid]  = (r < cnt) ? g_wgt[e * T + r] : 0.f;
    }
    __syncthreads();

    const int wid = tid >> 5, lane = tid & 31;
    const int g = lane >> 2, tg = lane & 3;
    const int m0w = (wid >> 1) * 32, n0w = (wid & 1) * 64;
    const uint32_t sb = (uint32_t)__cvta_generic_to_shared(smem);

    const float*  wd_base = Wd + (size_t)e * F * D + col0;
    const __half* h_base  = g_H + (size_t)e * RMAX * F;

    float acc[2][8][4];
#pragma unroll
    for (int mt = 0; mt < 2; mt++)
#pragma unroll
        for (int nt = 0; nt < 8; nt++)
#pragma unroll
            for (int j = 0; j < 4; j++) acc[mt][nt][j] = 0.f;

    const int lrow = lane & 15;
    const int lhk  = lane >> 4;
    uint4 ha[2];
    float4 rb[4];

    auto LDGC = [&](int c) {
#pragma unroll
        for (int i = 0; i < 2; i++) {
            int idx = tid + (i << 8);
            int m = idx >> 2, q8 = idx & 3;
            int r = row0 + m;
            ha[i] = (r < cnt)
                ? *(const uint4*)(h_base + (size_t)r * F + c * 32 + (q8 << 3))
                : make_uint4(0u, 0u, 0u, 0u);
        }
#pragma unroll
        for (int i = 0; i < 4; i++) {
            int idx = tid + (i << 8);
            int kk = idx >> 5, nq = idx & 31;
            rb[i] = *(const float4*)(wd_base + (size_t)(c * 32 + kk) * D + (nq << 2));
        }
    };
    auto STSC = [&](int buf) {
        char* fb = smem + 1024 + buf * GB_STAGE;
#pragma unroll
        for (int i = 0; i < 2; i++) {
            int idx = tid + (i << 8);
            int m = idx >> 2, q8 = idx & 3;
            *(uint4*)(fb + m * 64 + ((q8 ^ (m & 3)) << 4)) = ha[i];
        }
#pragma unroll
        for (int i = 0; i < 4; i++) {
            int idx = tid + (i << 8);
            int kk = idx >> 5, nq = idx & 31;
            *(uint2*)(fb + 8192 + kk * 256 +
                      ((((nq >> 1) ^ (kk & 7)) << 4) | ((nq & 1) << 3))) =
                make_uint2(packh2(rb[i].x, rb[i].y), packh2(rb[i].z, rb[i].w));
        }
    };
    auto COMPUTE = [&](int buf) {
        const uint32_t sA = sb + 1024 + buf * GB_STAGE;
        const uint32_t sB = sA + 8192;
#pragma unroll
        for (int ks = 0; ks < 2; ks++) {
            uint32_t a[2][4];
#pragma unroll
            for (int mt = 0; mt < 2; mt++) {
                int row = m0w + 16 * mt + lrow;
                int kc = (ks * 2 + lhk) ^ (row & 3);
                ldsm4(a[mt], sA + row * 64 + (kc << 4));
            }
#pragma unroll
            for (int p = 0; p < 4; p++) {
                int k = ks * 16 + lrow;
                int nc = ((n0w >> 3) + 2 * p + lhk) ^ (k & 7);
                uint32_t b[4];
                ldsm4t(b, sB + k * 256 + (nc << 4));
#pragma unroll
                for (int mt = 0; mt < 2; mt++) {
                    mma16(acc[mt][2 * p],     a[mt], b[0], b[1]);
                    mma16(acc[mt][2 * p + 1], a[mt], b[2], b[3]);
                }
            }
        }
    };

    LDGC(0);
    STSC(0);
    __syncthreads();
#pragma unroll 1
    for (int c = 1; c < 128; c++) {
        LDGC(c);
        COMPUTE((c - 1) & 1);
        STSC(c & 1);
        __syncthreads();
    }
    COMPUTE(1);

    // --- epilogue: weighted atomicAdd combine ---
#pragma unroll
    for (int mt = 0; mt < 2; mt++) {
#pragma unroll
        for (int rh = 0; rh < 2; rh++) {
            int rloc = m0w + 16 * mt + 8 * rh + g;
            if (row0 + rloc < cnt) {
                int tok = toks[rloc];
                float w = wts[rloc];
                float* orow = out + (size_t)tok * D + col0 + n0w + 2 * tg;
#pragma unroll
                for (int nt = 0; nt < 8; nt++) {
                    atomicAdd(orow + 8 * nt,     acc[mt][nt][2 * rh] * w);
                    atomicAdd(orow + 8 * nt + 1, acc[mt][nt][2 * rh + 1] * w);
                }
            }
        }
    }
}

// ---------------------------------------------------------------------------
// Launch
// ---------------------------------------------------------------------------
extern "C" void kernel_launch(void* const* d_in, const int* in_sizes, int n_in,
                              void* d_out, int out_size) {
    const float* x  = (const float*)d_in[0];
    const float* wr = (const float*)d_in[1];
    const float* wg = (const float*)d_in[2];
    const float* wu = (const float*)d_in[3];
    const float* wd = (const float*)d_in[4];
    float* out = (float*)d_out;

    cudaFuncSetAttribute(gemmA_h, cudaFuncAttributeMaxDynamicSharedMemorySize, GA_SMEM);
    cudaFuncSetAttribute(gemmB_h, cudaFuncAttributeMaxDynamicSharedMemorySize, GB_SMEM);

    cudaMemsetAsync(out, 0, (size_t)T * D * sizeof(float), 0);
    zero_cnt_kernel<<<1, 32>>>();
    router_kernel<<<T / 8, dim3(32, 8)>>>(x, wr);
    gemmA_h<<<dim3(T / 128, F / 64, E), 256, GA_SMEM>>>(x, wg, wu);
    gemmB_h<<<dim3(T / 128, D / 128, E), 256, GB_SMEM>>>(wd, out);
}

// round 5
// speedup vs baseline: 6.2910x; 1.2097x over previous
#include <cuda_runtime.h>
#include <cuda_fp16.h>
#include <math.h>
#include <stdint.h>

#define E 8
#define D 1024
#define F 4096
#define T 2048
#define RMAX 2048

// ---------------------------------------------------------------------------
// Device scratch
// ---------------------------------------------------------------------------
__device__ int   g_cnt[E];
__device__ int   g_tok[E * T];
__device__ float g_wgt[E * T];
__device__ __align__(16) __half g_H [(size_t)E * RMAX * F];   // 128 MB
__device__ __align__(16) __half g_Wg[(size_t)E * D * F];      // 67 MB
__device__ __align__(16) __half g_Wu[(size_t)E * D * F];      // 67 MB
__device__ __align__(16) __half g_Wd[(size_t)E * F * D];      // 67 MB
__device__ __align__(16) __half g_X [(size_t)T * D];          // 4 MB

// ---------------------------------------------------------------------------
// Helpers
// ---------------------------------------------------------------------------
__device__ __forceinline__ uint32_t packh2(float a, float b) {
    __half2 h = __floats2half2_rn(a, b);
    return *(uint32_t*)&h;
}
__device__ __forceinline__ void mma16(float c[4], const uint32_t a[4],
                                      uint32_t b0, uint32_t b1) {
    asm volatile(
        "mma.sync.aligned.m16n8k16.row.col.f32.f16.f16.f32 "
        "{%0,%1,%2,%3}, {%4,%5,%6,%7}, {%8,%9}, {%0,%1,%2,%3};"
        : "+f"(c[0]), "+f"(c[1]), "+f"(c[2]), "+f"(c[3])
        : "r"(a[0]), "r"(a[1]), "r"(a[2]), "r"(a[3]), "r"(b0), "r"(b1));
}
__device__ __forceinline__ void ldsm4(uint32_t r[4], uint32_t addr) {
    asm volatile("ldmatrix.sync.aligned.m8n8.x4.shared.b16 {%0,%1,%2,%3}, [%4];"
                 : "=r"(r[0]), "=r"(r[1]), "=r"(r[2]), "=r"(r[3]) : "r"(addr));
}
__device__ __forceinline__ void ldsm4t(uint32_t r[4], uint32_t addr) {
    asm volatile("ldmatrix.sync.aligned.m8n8.x4.trans.shared.b16 {%0,%1,%2,%3}, [%4];"
                 : "=r"(r[0]), "=r"(r[1]), "=r"(r[2]), "=r"(r[3]) : "r"(addr));
}
__device__ __forceinline__ void cpa16(uint32_t dst, const void* src) {
    asm volatile("cp.async.cg.shared.global [%0], [%1], 16;"
                 :: "r"(dst), "l"(src));
}
__device__ __forceinline__ void cpa16p(uint32_t dst, const void* src, int sz) {
    asm volatile("cp.async.cg.shared.global [%0], [%1], 16, %2;"
                 :: "r"(dst), "l"(src), "r"(sz));
}
#define CP_COMMIT asm volatile("cp.async.commit_group;")
#define CP_WAIT2  asm volatile("cp.async.wait_group 2;")

// ---------------------------------------------------------------------------
// fp32 -> fp16 conversion (weights + x), grid covers n4 float4s
// ---------------------------------------------------------------------------
__global__ void cvt_kernel(const float4* __restrict__ src, int sel, int n4) {
    int i = blockIdx.x * blockDim.x + threadIdx.x;
    if (i >= n4) return;
    __half* dst = (sel == 0) ? g_Wg : (sel == 1) ? g_Wu : (sel == 2) ? g_Wd : g_X;
    float4 v = src[i];
    *(uint2*)(dst + 4 * (size_t)i) =
        make_uint2(packh2(v.x, v.y), packh2(v.z, v.w));
}

// ---------------------------------------------------------------------------
// Router (unchanged — passing since R1)
// ---------------------------------------------------------------------------
__global__ void zero_cnt_kernel() {
    if (threadIdx.x < E) g_cnt[threadIdx.x] = 0;
}

__global__ void router_kernel(const float* __restrict__ x,
                              const float* __restrict__ wr) {
    int t = blockIdx.x * blockDim.y + threadIdx.y;
    if (t >= T) return;
    int lane = threadIdx.x;
    float acc[E];
#pragma unroll
    for (int e = 0; e < E; e++) acc[e] = 0.f;
    const float* xr = x + (size_t)t * D;
    for (int d = lane; d < D; d += 32) {
        float xv = xr[d];
        const float* w = wr + (size_t)d * E;
#pragma unroll
        for (int e = 0; e < E; e++) acc[e] = fmaf(xv, w[e], acc[e]);
    }
#pragma unroll
    for (int off = 16; off > 0; off >>= 1)
#pragma unroll
        for (int e = 0; e < E; e++)
            acc[e] += __shfl_down_sync(0xffffffffu, acc[e], off);

    if (lane == 0) {
        int i0 = 0;
#pragma unroll
        for (int e = 1; e < E; e++) if (acc[e] > acc[i0]) i0 = e;
        int i1 = (i0 == 0) ? 1 : 0;
#pragma unroll
        for (int e = 0; e < E; e++) {
            if (e == i0) continue;
            if (acc[e] > acc[i1]) i1 = e;
        }
        float w0 = 1.f / (1.f + expf(acc[i1] - acc[i0]));
        float w1 = 1.f - w0;
        int p0 = atomicAdd(&g_cnt[i0], 1);
        g_tok[i0 * T + p0] = t;  g_wgt[i0 * T + p0] = w0;
        int p1 = atomicAdd(&g_cnt[i1], 1);
        g_tok[i1 * T + p1] = t;  g_wgt[i1 * T + p1] = w1;
    }
}

// ---------------------------------------------------------------------------
// GEMM A: H = silu(X@Wg) * (X@Wu) -> g_H (fp16). cp.async 4-stage.
// CTA 128 x 64 (gate & up). Stage: A 8K + Bg 4K + Bu 4K = 16K.
// ---------------------------------------------------------------------------
#define GA_STAGE 16384
#define GA_SMEM (512 + 4 * GA_STAGE)
#define GA_C (D / 32)

__global__ void __launch_bounds__(256, 2) gemmA_h(
    const float* __restrict__, const float* __restrict__, const float* __restrict__)
{
    extern __shared__ char smem[];
    const int e = blockIdx.z;
    const int cnt = g_cnt[e];
    const int row0 = blockIdx.x * 128;
    if (row0 >= cnt) return;
    const int col0 = blockIdx.y * 64;

    int* toks = (int*)smem;
    const int tid = threadIdx.x;
    if (tid < 128) {
        int r = row0 + tid;
        toks[tid] = (r < cnt) ? g_tok[e * T + r] : -1;
    }
    __syncthreads();

    const int wid = tid >> 5, lane = tid & 31;
    const int g = lane >> 2, tg = lane & 3;
    const int m0w = (wid >> 1) * 32, n0w = (wid & 1) * 32;
    const uint32_t sb = (uint32_t)__cvta_generic_to_shared(smem);

    const __half* wgb = g_Wg + (size_t)e * D * F + col0;
    const __half* wub = g_Wu + (size_t)e * D * F + col0;

    // per-thread issue coords (fixed)
    const int am = tid >> 2, aq = tid & 3;            // A: rows, 16B slots
    const int bk = tid >> 3, bs = tid & 7;            // B: k rows, 16B slots
    const int atok0 = toks[am], atok1 = toks[am + 64];

    float accg[2][4][4], accu[2][4][4];
#pragma unroll
    for (int mt = 0; mt < 2; mt++)
#pragma unroll
        for (int nt = 0; nt < 4; nt++)
#pragma unroll
            for (int j = 0; j < 4; j++) { accg[mt][nt][j] = 0.f; accu[mt][nt][j] = 0.f; }

    const int lrow = lane & 15, lhk = lane >> 4;

    auto ISSUE = [&](int c, int st) {
        uint32_t base = sb + 512 + st * GA_STAGE;
        // A (gathered x, fp16): 128 rows x 4 slots = 512, 2 per thread
        {
            uint32_t d0 = base + am * 64 + ((aq ^ (am & 3)) << 4);
            const __half* s0 = g_X + (size_t)(atok0 >= 0 ? atok0 : 0) * D + c * 32 + aq * 8;
            cpa16p(d0, s0, atok0 >= 0 ? 16 : 0);
            int m1 = am + 64;
            uint32_t d1 = base + m1 * 64 + ((aq ^ (m1 & 3)) << 4);
            const __half* s1 = g_X + (size_t)(atok1 >= 0 ? atok1 : 0) * D + c * 32 + aq * 8;
            cpa16p(d1, s1, atok1 >= 0 ? 16 : 0);
        }
        // Bg/Bu: 32 k-rows x 8 slots = 256, 1 per thread each
        {
            uint32_t off = bk * 128 + ((bs ^ (bk & 7)) << 4);
            size_t go = (size_t)(c * 32 + bk) * F + bs * 8;
            cpa16(base + 8192 + off,  wgb + go);
            cpa16(base + 12288 + off, wub + go);
        }
    };
    auto COMPUTE = [&](int st) {
        const uint32_t sA = sb + 512 + st * GA_STAGE;
        const uint32_t sB = sA + 8192;
#pragma unroll
        for (int ks = 0; ks < 2; ks++) {
            uint32_t a[2][4];
#pragma unroll
            for (int mt = 0; mt < 2; mt++) {
                int row = m0w + 16 * mt + lrow;
                int kc = (ks * 2 + lhk) ^ (row & 3);
                ldsm4(a[mt], sA + row * 64 + (kc << 4));
            }
#pragma unroll
            for (int p = 0; p < 2; p++) {
                int k = ks * 16 + lrow;
                int nc = ((n0w >> 3) + 2 * p + lhk) ^ (k & 7);
                uint32_t bg[4], bu[4];
                uint32_t boff = k * 128 + (nc << 4);
                ldsm4t(bg, sB + boff);
                ldsm4t(bu, sB + 4096 + boff);
#pragma unroll
                for (int mt = 0; mt < 2; mt++) {
                    mma16(accg[mt][2 * p],     a[mt], bg[0], bg[1]);
                    mma16(accg[mt][2 * p + 1], a[mt], bg[2], bg[3]);
                    mma16(accu[mt][2 * p],     a[mt], bu[0], bu[1]);
                    mma16(accu[mt][2 * p + 1], a[mt], bu[2], bu[3]);
                }
            }
        }
    };

    ISSUE(0, 0); CP_COMMIT;
    ISSUE(1, 1); CP_COMMIT;
    ISSUE(2, 2); CP_COMMIT;
#pragma unroll 1
    for (int c = 0; c < GA_C; c++) {
        CP_WAIT2;
        __syncthreads();
        if (c + 3 < GA_C) ISSUE(c + 3, (c + 3) & 3);
        CP_COMMIT;
        COMPUTE(c & 3);
    }

    // --- epilogue: silu(gate)*up -> g_H (fp16) ---
#pragma unroll
    for (int mt = 0; mt < 2; mt++) {
#pragma unroll
        for (int rh = 0; rh < 2; rh++) {
            int r = row0 + m0w + 16 * mt + 8 * rh + g;
            if (r < cnt) {
                __half* hrow = g_H + ((size_t)e * RMAX + r) * F + col0 + n0w + 2 * tg;
#pragma unroll
                for (int nt = 0; nt < 4; nt++) {
                    float g0 = accg[mt][nt][2 * rh], g1 = accg[mt][nt][2 * rh + 1];
                    float u0 = accu[mt][nt][2 * rh], u1 = accu[mt][nt][2 * rh + 1];
                    float o0 = (g0 / (1.f + __expf(-g0))) * u0;
                    float o1 = (g1 / (1.f + __expf(-g1))) * u1;
                    *(__half2*)(hrow + 8 * nt) = __floats2half2_rn(o0, o1);
                }
            }
        }
    }
}

// ---------------------------------------------------------------------------
// GEMM B: out[tok] += w * (H @ Wd). cp.async 4-stage.
// CTA 128 x 128. Stage: A 8K + B 8K = 16K.
// ---------------------------------------------------------------------------
#define GB_STAGE 16384
#define GB_SMEM (1024 + 4 * GB_STAGE)
#define GB_C (F / 32)

__global__ void __launch_bounds__(256, 2) gemmB_h(
    const float* __restrict__, float* __restrict__ out)
{
    extern __shared__ char smem[];
    const int e = blockIdx.z;
    const int cnt = g_cnt[e];
    const int row0 = blockIdx.x * 128;
    if (row0 >= cnt) return;
    const int col0 = blockIdx.y * 128;

    int*   toks = (int*)smem;
    float* wts  = (float*)(smem + 512);
    const int tid = threadIdx.x;
    if (tid < 128) {
        int r = row0 + tid;
        toks[tid] = (r < cnt) ? g_tok[e * T + r] : 0;
        wts[tid]  = (r < cnt) ? g_wgt[e * T + r] : 0.f;
    }
    __syncthreads();

    const int wid = tid >> 5, lane = tid & 31;
    const int g = lane >> 2, tg = lane & 3;
    const int m0w = (wid >> 1) * 32, n0w = (wid & 1) * 64;
    const uint32_t sb = (uint32_t)__cvta_generic_to_shared(smem);

    const __half* wdb = g_Wd + (size_t)e * F * D + col0;
    const __half* hb  = g_H + (size_t)e * RMAX * F;

    const int am = tid >> 2, aq = tid & 3;
    const int bk = tid >> 4, bs = tid & 15;

    float acc[2][8][4];
#pragma unroll
    for (int mt = 0; mt < 2; mt++)
#pragma unroll
        for (int nt = 0; nt < 8; nt++)
#pragma unroll
            for (int j = 0; j < 4; j++) acc[mt][nt][j] = 0.f;

    const int lrow = lane & 15, lhk = lane >> 4;

    auto ISSUE = [&](int c, int st) {
        uint32_t base = sb + 1024 + st * GB_STAGE;
        // A (g_H rows): 128 rows x 4 slots, 2 per thread
#pragma unroll
        for (int i = 0; i < 2; i++) {
            int m = am + i * 64;
            int r = row0 + m;
            uint32_t dst = base + m * 64 + ((aq ^ (m & 3)) << 4);
            const __half* src = hb + (size_t)(r < cnt ? r : row0) * F + c * 32 + aq * 8;
            cpa16p(dst, src, r < cnt ? 16 : 0);
        }
        // B (Wd): 32 k-rows x 16 slots = 512, 2 per thread
#pragma unroll
        for (int i = 0; i < 2; i++) {
            int k = bk + i * 16;
            uint32_t dst = base + 8192 + k * 256 + ((bs ^ (k & 7)) << 4);
            cpa16(dst, wdb + (size_t)(c * 32 + k) * D + bs * 8);
        }
    };
    auto COMPUTE = [&](int st) {
        const uint32_t sA = sb + 1024 + st * GB_STAGE;
        const uint32_t sB = sA + 8192;
#pragma unroll
        for (int ks = 0; ks < 2; ks++) {
            uint32_t a[2][4];
#pragma unroll
            for (int mt = 0; mt < 2; mt++) {
                int row = m0w + 16 * mt + lrow;
                int kc = (ks * 2 + lhk) ^ (row & 3);
                ldsm4(a[mt], sA + row * 64 + (kc << 4));
            }
#pragma unroll
            for (int p = 0; p < 4; p++) {
                int k = ks * 16 + lrow;
                int nc = ((n0w >> 3) + 2 * p + lhk) ^ (k & 7);
                uint32_t b[4];
                ldsm4t(b, sB + k * 256 + (nc << 4));
#pragma unroll
                for (int mt = 0; mt < 2; mt++) {
                    mma16(acc[mt][2 * p],     a[mt], b[0], b[1]);
                    mma16(acc[mt][2 * p + 1], a[mt], b[2], b[3]);
                }
            }
        }
    };

    ISSUE(0, 0); CP_COMMIT;
    ISSUE(1, 1); CP_COMMIT;
    ISSUE(2, 2); CP_COMMIT;
#pragma unroll 1
    for (int c = 0; c < GB_C; c++) {
        CP_WAIT2;
        __syncthreads();
        if (c + 3 < GB_C) ISSUE(c + 3, (c + 3) & 3);
        CP_COMMIT;
        COMPUTE(c & 3);
    }

    // --- epilogue: weighted atomicAdd combine ---
#pragma unroll
    for (int mt = 0; mt < 2; mt++) {
#pragma unroll
        for (int rh = 0; rh < 2; rh++) {
            int rloc = m0w + 16 * mt + 8 * rh + g;
            if (row0 + rloc < cnt) {
                int tok = toks[rloc];
                float w = wts[rloc];
                float* orow = out + (size_t)tok * D + col0 + n0w + 2 * tg;
#pragma unroll
                for (int nt = 0; nt < 8; nt++) {
                    atomicAdd(orow + 8 * nt,     acc[mt][nt][2 * rh] * w);
                    atomicAdd(orow + 8 * nt + 1, acc[mt][nt][2 * rh + 1] * w);
                }
            }
        }
    }
}

// ---------------------------------------------------------------------------
// Launch
// ---------------------------------------------------------------------------
extern "C" void kernel_launch(void* const* d_in, const int* in_sizes, int n_in,
                              void* d_out, int out_size) {
    const float* x  = (const float*)d_in[0];
    const float* wr = (const float*)d_in[1];
    const float* wg = (const float*)d_in[2];
    const float* wu = (const float*)d_in[3];
    const float* wd = (const float*)d_in[4];
    float* out = (float*)d_out;

    cudaFuncSetAttribute(gemmA_h, cudaFuncAttributeMaxDynamicSharedMemorySize, GA_SMEM);
    cudaFuncSetAttribute(gemmB_h, cudaFuncAttributeMaxDynamicSharedMemorySize, GB_SMEM);

    cudaMemsetAsync(out, 0, (size_t)T * D * sizeof(float), 0);
    zero_cnt_kernel<<<1, 32>>>();
    router_kernel<<<T / 8, dim3(32, 8)>>>(x, wr);

    const int nw4 = E * D * F / 4;       // 8388608
    cvt_kernel<<<nw4 / 256, 256>>>((const float4*)wg, 0, nw4);
    cvt_kernel<<<nw4 / 256, 256>>>((const float4*)wu, 1, nw4);
    cvt_kernel<<<nw4 / 256, 256>>>((const float4*)wd, 2, nw4);
    const int nx4 = T * D / 4;           // 524288
    cvt_kernel<<<nx4 / 256, 256>>>((const float4*)x, 3, nx4);

    gemmA_h<<<dim3(T / 128, F / 64, E), 256, GA_SMEM>>>(x, x, x);
    gemmB_h<<<dim3(T / 128, D / 128, E), 256, GB_SMEM>>>(x, out);
}

// round 7
// speedup vs baseline: 6.4397x; 1.0236x over previous
#include <cuda_runtime.h>
#include <cuda_fp16.h>
#include <math.h>
#include <stdint.h>

#define E 8
#define D 1024
#define F 4096
#define T 2048
#define RMAX 2048
#define KSPLIT 4

// ---------------------------------------------------------------------------
// Device scratch
// ---------------------------------------------------------------------------
__device__ int   g_cnt[E];
__device__ int   g_tok[E * T];
__device__ float g_wgt[E * T];
__device__ __align__(16) __half g_H [(size_t)E * RMAX * F];   // 128 MB
__device__ __align__(16) __half g_Wg[(size_t)E * D * F];      // 67 MB
__device__ __align__(16) __half g_Wu[(size_t)E * D * F];      // 67 MB
__device__ __align__(16) __half g_Wd[(size_t)E * F * D];      // 67 MB
__device__ __align__(16) __half g_X [(size_t)T * D];          // 4 MB

// ---------------------------------------------------------------------------
// Helpers
// ---------------------------------------------------------------------------
__device__ __forceinline__ uint32_t packh2(float a, float b) {
    __half2 h = __floats2half2_rn(a, b);
    return *(uint32_t*)&h;
}
__device__ __forceinline__ void mma16(float c[4], const uint32_t a[4],
                                      uint32_t b0, uint32_t b1) {
    asm volatile(
        "mma.sync.aligned.m16n8k16.row.col.f32.f16.f16.f32 "
        "{%0,%1,%2,%3}, {%4,%5,%6,%7}, {%8,%9}, {%0,%1,%2,%3};"
        : "+f"(c[0]), "+f"(c[1]), "+f"(c[2]), "+f"(c[3])
        : "r"(a[0]), "r"(a[1]), "r"(a[2]), "r"(a[3]), "r"(b0), "r"(b1));
}
__device__ __forceinline__ void ldsm4(uint32_t r[4], uint32_t addr) {
    asm volatile("ldmatrix.sync.aligned.m8n8.x4.shared.b16 {%0,%1,%2,%3}, [%4];"
                 : "=r"(r[0]), "=r"(r[1]), "=r"(r[2]), "=r"(r[3]) : "r"(addr));
}
__device__ __forceinline__ void ldsm4t(uint32_t r[4], uint32_t addr) {
    asm volatile("ldmatrix.sync.aligned.m8n8.x4.trans.shared.b16 {%0,%1,%2,%3}, [%4];"
                 : "=r"(r[0]), "=r"(r[1]), "=r"(r[2]), "=r"(r[3]) : "r"(addr));
}
__device__ __forceinline__ void cpa16(uint32_t dst, const void* src) {
    asm volatile("cp.async.cg.shared.global [%0], [%1], 16;"
                 :: "r"(dst), "l"(src));
}
__device__ __forceinline__ void cpa16p(uint32_t dst, const void* src, int sz) {
    asm volatile("cp.async.cg.shared.global [%0], [%1], 16, %2;"
                 :: "r"(dst), "l"(src), "r"(sz));
}
#define CP_COMMIT asm volatile("cp.async.commit_group;")
#define CP_WAIT2  asm volatile("cp.async.wait_group 2;")

// ---------------------------------------------------------------------------
// Fused fp32 -> fp16 conversion: Wg | Wu | Wd | X, 32 bytes in per thread
// ---------------------------------------------------------------------------
#define W8 ((size_t)E * D * F / 8)     // 4194304 8-elem groups per weight
#define X8 ((size_t)T * D / 8)         // 262144
#define CVT_TOT (3 * W8 + X8)          // 12845056

__global__ void cvt_all(const float4* __restrict__ wg,
                        const float4* __restrict__ wu,
                        const float4* __restrict__ wd,
                        const float4* __restrict__ x) {
    size_t i = (size_t)blockIdx.x * blockDim.x + threadIdx.x;
    if (i >= CVT_TOT) return;
    const float4* src;
    __half* dst;
    size_t off;
    if (i < W8)            { src = wg; dst = g_Wg; off = i; }
    else if (i < 2 * W8)   { src = wu; dst = g_Wu; off = i - W8; }
    else if (i < 3 * W8)   { src = wd; dst = g_Wd; off = i - 2 * W8; }
    else                   { src = x;  dst = g_X;  off = i - 3 * W8; }
    float4 a = src[2 * off];
    float4 b = src[2 * off + 1];
    uint4 o = make_uint4(packh2(a.x, a.y), packh2(a.z, a.w),
                         packh2(b.x, b.y), packh2(b.z, b.w));
    *(uint4*)(dst + 8 * off) = o;
}

// ---------------------------------------------------------------------------
// Router (unchanged — passing since R1)
// ---------------------------------------------------------------------------
__global__ void zero_cnt_kernel() {
    if (threadIdx.x < E) g_cnt[threadIdx.x] = 0;
}

__global__ void router_kernel(const float* __restrict__ x,
                              const float* __restrict__ wr) {
    int t = blockIdx.x * blockDim.y + threadIdx.y;
    if (t >= T) return;
    int lane = threadIdx.x;
    float acc[E];
#pragma unroll
    for (int e = 0; e < E; e++) acc[e] = 0.f;
    const float* xr = x + (size_t)t * D;
    for (int d = lane; d < D; d += 32) {
        float xv = xr[d];
        const float* w = wr + (size_t)d * E;
#pragma unroll
        for (int e = 0; e < E; e++) acc[e] = fmaf(xv, w[e], acc[e]);
    }
#pragma unroll
    for (int off = 16; off > 0; off >>= 1)
#pragma unroll
        for (int e = 0; e < E; e++)
            acc[e] += __shfl_down_sync(0xffffffffu, acc[e], off);

    if (lane == 0) {
        int i0 = 0;
#pragma unroll
        for (int e = 1; e < E; e++) if (acc[e] > acc[i0]) i0 = e;
        int i1 = (i0 == 0) ? 1 : 0;
#pragma unroll
        for (int e = 0; e < E; e++) {
            if (e == i0) continue;
            if (acc[e] > acc[i1]) i1 = e;
        }
        float w0 = 1.f / (1.f + expf(acc[i1] - acc[i0]));
        float w1 = 1.f - w0;
        int p0 = atomicAdd(&g_cnt[i0], 1);
        g_tok[i0 * T + p0] = t;  g_wgt[i0 * T + p0] = w0;
        int p1 = atomicAdd(&g_cnt[i1], 1);
        g_tok[i1 * T + p1] = t;  g_wgt[i1 * T + p1] = w1;
    }
}

// ---------------------------------------------------------------------------
// GEMM A: H = silu(X@Wg) * (X@Wu) -> g_H (fp16). cp.async 4-stage.
// CTA 128 x 64 (gate & up). Stage: A 8K + Bg 4K + Bu 4K = 16K.
// ---------------------------------------------------------------------------
#define GA_STAGE 16384
#define GA_SMEM (512 + 4 * GA_STAGE)
#define GA_C (D / 32)

__global__ void __launch_bounds__(256, 2) gemmA_h(
    const float* __restrict__, const float* __restrict__, const float* __restrict__)
{
    extern __shared__ char smem[];
    const int e = blockIdx.z;
    const int cnt = g_cnt[e];
    const int row0 = blockIdx.x * 128;
    if (row0 >= cnt) return;
    const int col0 = blockIdx.y * 64;

    int* toks = (int*)smem;
    const int tid = threadIdx.x;
    if (tid < 128) {
        int r = row0 + tid;
        toks[tid] = (r < cnt) ? g_tok[e * T + r] : -1;
    }
    __syncthreads();

    const int wid = tid >> 5, lane = tid & 31;
    const int g = lane >> 2, tg = lane & 3;
    const int m0w = (wid >> 1) * 32, n0w = (wid & 1) * 32;
    const uint32_t sb = (uint32_t)__cvta_generic_to_shared(smem);

    const __half* wgb = g_Wg + (size_t)e * D * F + col0;
    const __half* wub = g_Wu + (size_t)e * D * F + col0;

    const int am = tid >> 2, aq = tid & 3;
    const int bk = tid >> 3, bs = tid & 7;
    const int atok0 = toks[am], atok1 = toks[am + 64];

    float accg[2][4][4], accu[2][4][4];
#pragma unroll
    for (int mt = 0; mt < 2; mt++)
#pragma unroll
        for (int nt = 0; nt < 4; nt++)
#pragma unroll
            for (int j = 0; j < 4; j++) { accg[mt][nt][j] = 0.f; accu[mt][nt][j] = 0.f; }

    const int lrow = lane & 15, lhk = lane >> 4;

    auto ISSUE = [&](int c, int st) {
        uint32_t base = sb + 512 + st * GA_STAGE;
        {
            uint32_t d0 = base + am * 64 + ((aq ^ (am & 3)) << 4);
            const __half* s0 = g_X + (size_t)(atok0 >= 0 ? atok0 : 0) * D + c * 32 + aq * 8;
            cpa16p(d0, s0, atok0 >= 0 ? 16 : 0);
            int m1 = am + 64;
            uint32_t d1 = base + m1 * 64 + ((aq ^ (m1 & 3)) << 4);
            const __half* s1 = g_X + (size_t)(atok1 >= 0 ? atok1 : 0) * D + c * 32 + aq * 8;
            cpa16p(d1, s1, atok1 >= 0 ? 16 : 0);
        }
        {
            uint32_t off = bk * 128 + ((bs ^ (bk & 7)) << 4);
            size_t go = (size_t)(c * 32 + bk) * F + bs * 8;
            cpa16(base + 8192 + off,  wgb + go);
            cpa16(base + 12288 + off, wub + go);
        }
    };
    auto COMPUTE = [&](int st) {
        const uint32_t sA = sb + 512 + st * GA_STAGE;
        const uint32_t sB = sA + 8192;
#pragma unroll
        for (int ks = 0; ks < 2; ks++) {
            uint32_t a[2][4];
#pragma unroll
            for (int mt = 0; mt < 2; mt++) {
                int row = m0w + 16 * mt + lrow;
                int kc = (ks * 2 + lhk) ^ (row & 3);
                ldsm4(a[mt], sA + row * 64 + (kc << 4));
            }
#pragma unroll
            for (int p = 0; p < 2; p++) {
                int k = ks * 16 + lrow;
                int nc = ((n0w >> 3) + 2 * p + lhk) ^ (k & 7);
                uint32_t bg[4], bu[4];
                uint32_t boff = k * 128 + (nc << 4);
                ldsm4t(bg, sB + boff);
                ldsm4t(bu, sB + 4096 + boff);
#pragma unroll
                for (int mt = 0; mt < 2; mt++) {
                    mma16(accg[mt][2 * p],     a[mt], bg[0], bg[1]);
                    mma16(accg[mt][2 * p + 1], a[mt], bg[2], bg[3]);
                    mma16(accu[mt][2 * p],     a[mt], bu[0], bu[1]);
                    mma16(accu[mt][2 * p + 1], a[mt], bu[2], bu[3]);
                }
            }
        }
    };

    ISSUE(0, 0); CP_COMMIT;
    ISSUE(1, 1); CP_COMMIT;
    ISSUE(2, 2); CP_COMMIT;
#pragma unroll 1
    for (int c = 0; c < GA_C; c++) {
        CP_WAIT2;
        __syncthreads();
        if (c + 3 < GA_C) ISSUE(c + 3, (c + 3) & 3);
        CP_COMMIT;
        COMPUTE(c & 3);
    }

    // --- epilogue: silu(gate)*up -> g_H (fp16) ---
#pragma unroll
    for (int mt = 0; mt < 2; mt++) {
#pragma unroll
        for (int rh = 0; rh < 2; rh++) {
            int r = row0 + m0w + 16 * mt + 8 * rh + g;
            if (r < cnt) {
                __half* hrow = g_H + ((size_t)e * RMAX + r) * F + col0 + n0w + 2 * tg;
#pragma unroll
                for (int nt = 0; nt < 4; nt++) {
                    float g0 = accg[mt][nt][2 * rh], g1 = accg[mt][nt][2 * rh + 1];
                    float u0 = accu[mt][nt][2 * rh], u1 = accu[mt][nt][2 * rh + 1];
                    float o0 = (g0 / (1.f + __expf(-g0))) * u0;
                    float o1 = (g1 / (1.f + __expf(-g1))) * u1;
                    *(__half2*)(hrow + 8 * nt) = __floats2half2_rn(o0, o1);
                }
            }
        }
    }
}

// ---------------------------------------------------------------------------
// GEMM B: out[tok] += w * (H @ Wd). cp.async 4-stage, split-K = 4.
// CTA 128 x 128, K-slice 1024. Stage: A 8K + B 8K = 16K.
// ---------------------------------------------------------------------------
#define GB_STAGE 16384
#define GB_SMEM (1024 + 4 * GB_STAGE)
#define GB_C (F / 32 / KSPLIT)     // 32 chunks per CTA

__global__ void __launch_bounds__(256, 2) gemmB_h(
    const float* __restrict__, float* __restrict__ out)
{
    extern __shared__ char smem[];
    const int e = blockIdx.z;
    const int cnt = g_cnt[e];
    const int row0 = blockIdx.x * 128;
    if (row0 >= cnt) return;
    const int col0 = (blockIdx.y >> 2) * 128;
    const int kchunk0 = (blockIdx.y & 3) * GB_C;

    int*   toks = (int*)smem;
    float* wts  = (float*)(smem + 512);
    const int tid = threadIdx.x;
    if (tid < 128) {
        int r = row0 + tid;
        toks[tid] = (r < cnt) ? g_tok[e * T + r] : 0;
        wts[tid]  = (r < cnt) ? g_wgt[e * T + r] : 0.f;
    }
    __syncthreads();

    const int wid = tid >> 5, lane = tid & 31;
    const int g = lane >> 2, tg = lane & 3;
    const int m0w = (wid >> 1) * 32, n0w = (wid & 1) * 64;
    const uint32_t sb = (uint32_t)__cvta_generic_to_shared(smem);

    const __half* wdb = g_Wd + (size_t)e * F * D + col0;
    const __half* hb  = g_H + (size_t)e * RMAX * F;

    const int am = tid >> 2, aq = tid & 3;
    const int bk = tid >> 4, bs = tid & 15;

    float acc[2][8][4];
#pragma unroll
    for (int mt = 0; mt < 2; mt++)
#pragma unroll
        for (int nt = 0; nt < 8; nt++)
#pragma unroll
            for (int j = 0; j < 4; j++) acc[mt][nt][j] = 0.f;

    const int lrow = lane & 15, lhk = lane >> 4;

    auto ISSUE = [&](int c, int st) {
        uint32_t base = sb + 1024 + st * GB_STAGE;
        int kc = kchunk0 + c;
#pragma unroll
        for (int i = 0; i < 2; i++) {
            int m = am + i * 64;
            int r = row0 + m;
            uint32_t dst = base + m * 64 + ((aq ^ (m & 3)) << 4);
            const __half* src = hb + (size_t)(r < cnt ? r : row0) * F + kc * 32 + aq * 8;
            cpa16p(dst, src, r < cnt ? 16 : 0);
        }
#pragma unroll
        for (int i = 0; i < 2; i++) {
            int k = bk + i * 16;
            uint32_t dst = base + 8192 + k * 256 + ((bs ^ (k & 7)) << 4);
            cpa16(dst, wdb + (size_t)(kc * 32 + k) * D + bs * 8);
        }
    };
    auto COMPUTE = [&](int st) {
        const uint32_t sA = sb + 1024 + st * GB_STAGE;
        const uint32_t sB = sA + 8192;
#pragma unroll
        for (int ks = 0; ks < 2; ks++) {
            uint32_t a[2][4];
#pragma unroll
            for (int mt = 0; mt < 2; mt++) {
                int row = m0w + 16 * mt + lrow;
                int kc = (ks * 2 + lhk) ^ (row & 3);
                ldsm4(a[mt], sA + row * 64 + (kc << 4));
            }
#pragma unroll
            for (int p = 0; p < 4; p++) {
                int k = ks * 16 + lrow;
                int nc = ((n0w >> 3) + 2 * p + lhk) ^ (k & 7);
                uint32_t b[4];
                ldsm4t(b, sB + k * 256 + (nc << 4));
#pragma unroll
                for (int mt = 0; mt < 2; mt++) {
                    mma16(acc[mt][2 * p],     a[mt], b[0], b[1]);
                    mma16(acc[mt][2 * p + 1], a[mt], b[2], b[3]);
                }
            }
        }
    };

    ISSUE(0, 0); CP_COMMIT;
    ISSUE(1, 1); CP_COMMIT;
    ISSUE(2, 2); CP_COMMIT;
#pragma unroll 1
    for (int c = 0; c < GB_C; c++) {
        CP_WAIT2;
        __syncthreads();
        if (c + 3 < GB_C) ISSUE(c + 3, (c + 3) & 3);
        CP_COMMIT;
        COMPUTE(c & 3);
    }

    // --- epilogue: weighted atomicAdd combine (split-K partial sums) ---
#pragma unroll
    for (int mt = 0; mt < 2; mt++) {
#pragma unroll
        for (int rh = 0; rh < 2; rh++) {
            int rloc = m0w + 16 * mt + 8 * rh + g;
            if (row0 + rloc < cnt) {
                int tok = toks[rloc];
                float w = wts[rloc];
                float* orow = out + (size_t)tok * D + col0 + n0w + 2 * tg;
#pragma unroll
                for (int nt = 0; nt < 8; nt++) {
                    atomicAdd(orow + 8 * nt,     acc[mt][nt][2 * rh] * w);
                    atomicAdd(orow + 8 * nt + 1, acc[mt][nt][2 * rh + 1] * w);
                }
            }
        }
    }
}

// ---------------------------------------------------------------------------
// Launch
// ---------------------------------------------------------------------------
extern "C" void kernel_launch(void* const* d_in, const int* in_sizes, int n_in,
                              void* d_out, int out_size) {
    const float* x  = (const float*)d_in[0];
    const float* wr = (const float*)d_in[1];
    const float* wg = (const float*)d_in[2];
    const float* wu = (const float*)d_in[3];
    const float* wd = (const float*)d_in[4];
    float* out = (float*)d_out;

    cudaFuncSetAttribute(gemmA_h, cudaFuncAttributeMaxDynamicSharedMemorySize, GA_SMEM);
    cudaFuncSetAttribute(gemmB_h, cudaFuncAttributeMaxDynamicSharedMemorySize, GB_SMEM);

    cudaMemsetAsync(out, 0, (size_t)T * D * sizeof(float), 0);
    zero_cnt_kernel<<<1, 32>>>();
    router_kernel<<<T / 8, dim3(32, 8)>>>(x, wr);

    cvt_all<<<(int)((CVT_TOT + 255) / 256), 256>>>(
        (const float4*)wg, (const float4*)wu, (const float4*)wd, (const float4*)x);

    gemmA_h<<<dim3(T / 128, F / 64, E), 256, GA_SMEM>>>(x, x, x);
    gemmB_h<<<dim3(T / 128, (D / 128) * KSPLIT, E), 256, GB_SMEM>>>(x, out);
}